// round 14
// baseline (speedup 1.0000x reference)
#include <cuda_runtime.h>

#define NN 256
#define TT 200
#define SS 100
#define CH 64                          // columns per scan CTA
#define NSTAGE 16                      // ring slots (power of two)
#define STAGE_FLOATS (CH * 3 * 2)      // 384 floats = 1536 B per stage
#define STEP_STRIDE ((size_t)2 * NN * NN * 3)   // floats, a[t] -> a[t+2]

// F[n][t] scratch, transposed so scan CTAs read their row contiguously
__device__ float gF[NN * TT];

// ---------------- Kernel 1: F[n][t] = exp(-dot(w[t,n,:], ev[t,n,:]) * time[t&1]) ----------------
__global__ __launch_bounds__(256)
void f_kernel(const float* __restrict__ time,
              const float* __restrict__ ev,
              const float* __restrict__ w)
{
#if __CUDA_ARCH__ >= 900
    cudaTriggerProgrammaticLaunchCompletion();   // let the scan's prologue overlap our tail
#endif
    const int p    = blockIdx.x * 8 + (threadIdx.x >> 5);   // pair index 0..25599
    const int lane = threadIdx.x & 31;
    const int t  = p >> 7;            // 0..199
    const int n0 = (p & 127) * 2;     // 0,2,..,254

    const float4* wa = (const float4*)(w  + ((size_t)t * NN + n0) * NN);
    const float4* ea = (const float4*)(ev + ((size_t)t * NN + n0) * NN);
    const float4* wb = wa + (NN / 4);
    const float4* eb = ea + (NN / 4);

    // issue all 8 loads (streaming, touch-once) before any dependent math
    float4 w0 = __ldcs(wa + lane), w1 = __ldcs(wa + lane + 32);
    float4 e0 = __ldcs(ea + lane), e1 = __ldcs(ea + lane + 32);
    float4 w2 = __ldcs(wb + lane), w3 = __ldcs(wb + lane + 32);
    float4 e2 = __ldcs(eb + lane), e3 = __ldcs(eb + lane + 32);

    float accA = w0.x*e0.x + w0.y*e0.y + w0.z*e0.z + w0.w*e0.w
               + w1.x*e1.x + w1.y*e1.y + w1.z*e1.z + w1.w*e1.w;
    float accB = w2.x*e2.x + w2.y*e2.y + w2.z*e2.z + w2.w*e2.w
               + w3.x*e3.x + w3.y*e3.y + w3.z*e3.z + w3.w*e3.w;
    #pragma unroll
    for (int off = 16; off; off >>= 1) {
        accA += __shfl_xor_sync(0xffffffffu, accA, off);
        accB += __shfl_xor_sync(0xffffffffu, accB, off);
    }
    if (lane == 0) {
        const float tt = (t & 1) ? time[1] : time[0];
        gF[(size_t)n0 * TT + t]       = __expf(-accA * tt);
        gF[(size_t)(n0 + 1) * TT + t] = __expf(-accB * tt);
    }
}

// ---------------- Kernel 2: scan, 2 steps/interval, 14-stage PDL prologue, lean softmax ----------------
__global__ __launch_bounds__(64)
void scan_kernel(const float* __restrict__ u_begin,
                 const float* __restrict__ a,
                 const float* __restrict__ lw,
                 const float* __restrict__ lb,
                 float* __restrict__ out)
{
    __shared__ float stages[NSTAGE][STAGE_FLOATS];   // 24576 B
    __shared__ float Fs[TT];                         // 800 B

    const int n   = blockIdx.x >> 2;          // row (node)
    const int c0  = (blockIdx.x & 3) * CH;    // column chunk base
    const int tid = threadIdx.x;              // 0..63

    const size_t slice = (size_t)NN * NN * 3;
    const float* abase = a + ((size_t)n * NN + c0) * 3;

    // per-thread cp.async sources (advance by STEP_STRIDE per stage)
    const float* pA = abase + ((tid < 48) ? (size_t)tid * 4
                                          : slice + (size_t)(tid - 48) * 4);
    const float* pB = abase + slice + (size_t)(tid + 16) * 4;   // used when tid<32

    const unsigned smem0 = (unsigned)__cvta_generic_to_shared(&stages[0][0]);

    auto issue_stage = [&](int s) {
        unsigned off = smem0 + (unsigned)(s & (NSTAGE - 1)) * (STAGE_FLOATS * 4);
        asm volatile("cp.async.cg.shared.global [%0], [%1], 16;\n"
                     :: "r"(off + tid * 16), "l"(pA));
        if (tid < 32)
            asm volatile("cp.async.cg.shared.global [%0], [%1], 16;\n"
                         :: "r"(off + (64 + tid) * 16), "l"(pB));
        pA += STEP_STRIDE;
        pB += STEP_STRIDE;
    };

    // ---- pre-sync prologue (independent of gF): 14 stages in 7 paired groups ----
    // max safe depth: refill in steady state targets slots consumed LAST interval
    #pragma unroll
    for (int g = 0; g < 7; g++) {
        issue_stage(2 * g);
        issue_stage(2 * g + 1);
        asm volatile("cp.async.commit_group;\n" ::: "memory");
    }
    const float lw0 = lw[n * 3 + 0], lw1 = lw[n * 3 + 1], lw2 = lw[n * 3 + 2];
    const float lbn = lb[n];
    const float* up = u_begin + ((size_t)n * NN + c0 + tid) * 3;
    float u0 = up[0], u1 = up[1], u2 = up[2];
    float* op = out + (size_t)n * NN + c0 + tid;

#if __CUDA_ARCH__ >= 900
    cudaGridDependencySynchronize();          // wait for f_kernel before touching gF
#endif
    for (int t = tid; t < TT; t += CH) Fs[t] = gF[(size_t)n * TT + t];

    asm volatile("cp.async.wait_group 6;\n" ::: "memory");   // pair 0 (stages 0,1) arrived
    __syncthreads();                                          // (also publishes Fs)

    for (int i = 0; i < SS / 2; i++) {
        const int s0 = 2 * i;

        #pragma unroll
        for (int j = 0; j < 2; j++) {
            const int s = s0 + j;
            const float* st0 = stages[s & (NSTAGE - 1)];
            const float* st1 = st0 + CH * 3;
            const float a00 = st0[3 * tid], a01 = st0[3 * tid + 1], a02 = st0[3 * tid + 2];
            const float a10 = st1[3 * tid], a11 = st1[3 * tid + 1], a12 = st1[3 * tid + 2];
            const float2 fp = *(const float2*)&Fs[2 * s];     // one LDS.64, 8B-aligned
            const float f0 = fp.x, f1 = fp.y;

            float l0 = u0 + a00 * f0 + a10 * f1;
            float l1 = u1 + a01 * f0 + a11 * f1;
            float l2 = u2 + a02 * f0 + a12 * f1;
            // l0-referenced softmax: softmax = (1, e^d1, e^d2) / (1 + e^d1 + e^d2)
            float e1 = __expf(l1 - l0);
            float e2 = __expf(l2 - l0);
            float inv = __fdividef(1.0f, 1.0f + e1 + e2);
            u0 = inv;
            u1 = e1 * inv;
            u2 = e2 * inv;
            __stcs(op + (size_t)s * NN * NN,
                   fmaf(inv, lw0 + e1 * lw1 + e2 * lw2, lbn));
        }

        // refill pair (s0+14, s0+15) -> slots (s0-2)&15,(s0-1)&15: consumed LAST interval,
        // write-after-read protected by last interval's __syncthreads
        if (s0 + 14 < SS) issue_stage(s0 + 14);
        if (s0 + 15 < SS) issue_stage(s0 + 15);
        asm volatile("cp.async.commit_group;\n" ::: "memory");   // (empty near tail)
        asm volatile("cp.async.wait_group 6;\n" ::: "memory");   // pair (s0+2,s0+3) arrived
        __syncthreads();
    }
}

extern "C" void kernel_launch(void* const* d_in, const int* in_sizes, int n_in,
                              void* d_out, int out_size)
{
    const float* time    = (const float*)d_in[0];   // [2]
    const float* ev      = (const float*)d_in[1];   // [201,256,256]
    const float* u_begin = (const float*)d_in[2];   // [256,256,3]
    const float* a       = (const float*)d_in[3];   // [200,256,256,3]
    const float* w       = (const float*)d_in[4];   // [200,256,1,256]
    const float* lw      = (const float*)d_in[5];   // [256,3]
    const float* lb      = (const float*)d_in[6];   // [256]

    float* out = (float*)d_out;                     // [100,256,256]

    f_kernel<<<(TT * NN / 2) / 8, 256>>>(time, ev, w);

    // PDL: scan launches early; its 14-stage cp.async prologue overlaps f_kernel.
    cudaLaunchConfig_t cfg = {};
    cfg.gridDim  = dim3(NN * 4);
    cfg.blockDim = dim3(CH);
    cudaLaunchAttribute attr[1];
    attr[0].id = cudaLaunchAttributeProgrammaticStreamSerialization;
    attr[0].val.programmaticStreamSerializationAllowed = 1;
    cfg.attrs = attr;
    cfg.numAttrs = 1;
    cudaLaunchKernelEx(&cfg, scan_kernel, u_begin, a, lw, lb, out);
}

// round 15
// speedup vs baseline: 1.0335x; 1.0335x over previous
#include <cuda_runtime.h>

#define NN 256
#define TT 200
#define SS 100
#define CH 64                          // columns per scan CTA
#define NSTAGE 16                      // ring slots (power of two)
#define STAGE_FLOATS (CH * 3 * 2)      // 384 floats = 1536 B per stage
#define STEP_STRIDE ((size_t)2 * NN * NN * 3)   // floats, a[t] -> a[t+2]

// F[n][t] scratch, transposed so scan CTAs read their row contiguously
__device__ float gF[NN * TT];

// ---------------- Kernel 1: F[n][t] = exp(-dot(w[t,n,:], ev[t,n,:]) * time[t&1]) ----------------
__global__ __launch_bounds__(256)
void f_kernel(const float* __restrict__ time,
              const float* __restrict__ ev,
              const float* __restrict__ w)
{
#if __CUDA_ARCH__ >= 900
    cudaTriggerProgrammaticLaunchCompletion();   // let the scan's prologue overlap our tail
#endif
    const int p    = blockIdx.x * 8 + (threadIdx.x >> 5);   // pair index 0..25599
    const int lane = threadIdx.x & 31;
    const int t  = p >> 7;            // 0..199
    const int n0 = (p & 127) * 2;     // 0,2,..,254

    const float4* wa = (const float4*)(w  + ((size_t)t * NN + n0) * NN);
    const float4* ea = (const float4*)(ev + ((size_t)t * NN + n0) * NN);
    const float4* wb = wa + (NN / 4);
    const float4* eb = ea + (NN / 4);

    // issue all 8 loads (streaming, touch-once) before any dependent math
    float4 w0 = __ldcs(wa + lane), w1 = __ldcs(wa + lane + 32);
    float4 e0 = __ldcs(ea + lane), e1 = __ldcs(ea + lane + 32);
    float4 w2 = __ldcs(wb + lane), w3 = __ldcs(wb + lane + 32);
    float4 e2 = __ldcs(eb + lane), e3 = __ldcs(eb + lane + 32);

    float accA = w0.x*e0.x + w0.y*e0.y + w0.z*e0.z + w0.w*e0.w
               + w1.x*e1.x + w1.y*e1.y + w1.z*e1.z + w1.w*e1.w;
    float accB = w2.x*e2.x + w2.y*e2.y + w2.z*e2.z + w2.w*e2.w
               + w3.x*e3.x + w3.y*e3.y + w3.z*e3.z + w3.w*e3.w;
    #pragma unroll
    for (int off = 16; off; off >>= 1) {
        accA += __shfl_xor_sync(0xffffffffu, accA, off);
        accB += __shfl_xor_sync(0xffffffffu, accB, off);
    }
    if (lane == 0) {
        const float tt = (t & 1) ? time[1] : time[0];
        gF[(size_t)n0 * TT + t]       = __expf(-accA * tt);
        gF[(size_t)(n0 + 1) * TT + t] = __expf(-accB * tt);
    }
}

// ---------------- Kernel 2: scan — R8 pipeline (12-stage, wait 5) + R12 lean softmax ----------------
__global__ __launch_bounds__(64)
void scan_kernel(const float* __restrict__ u_begin,
                 const float* __restrict__ a,
                 const float* __restrict__ lw,
                 const float* __restrict__ lb,
                 float* __restrict__ out)
{
    __shared__ float stages[NSTAGE][STAGE_FLOATS];   // 24576 B
    __shared__ float Fs[TT];                         // 800 B

    const int n   = blockIdx.x >> 2;          // row (node)
    const int c0  = (blockIdx.x & 3) * CH;    // column chunk base
    const int tid = threadIdx.x;              // 0..63

    const size_t slice = (size_t)NN * NN * 3;
    const float* abase = a + ((size_t)n * NN + c0) * 3;

    // per-thread cp.async sources (advance by STEP_STRIDE per stage)
    const float* pA = abase + ((tid < 48) ? (size_t)tid * 4
                                          : slice + (size_t)(tid - 48) * 4);
    const float* pB = abase + slice + (size_t)(tid + 16) * 4;   // used when tid<32

    const unsigned smem0 = (unsigned)__cvta_generic_to_shared(&stages[0][0]);

    auto issue_stage = [&](int s) {
        unsigned off = smem0 + (unsigned)(s & (NSTAGE - 1)) * (STAGE_FLOATS * 4);
        asm volatile("cp.async.cg.shared.global [%0], [%1], 16;\n"
                     :: "r"(off + tid * 16), "l"(pA));
        if (tid < 32)
            asm volatile("cp.async.cg.shared.global [%0], [%1], 16;\n"
                         :: "r"(off + (64 + tid) * 16), "l"(pB));
        pA += STEP_STRIDE;
        pB += STEP_STRIDE;
    };

    // ---- pre-sync prologue (independent of gF): 12 stages in 6 paired groups ----
    #pragma unroll
    for (int g = 0; g < 6; g++) {
        issue_stage(2 * g);
        issue_stage(2 * g + 1);
        asm volatile("cp.async.commit_group;\n" ::: "memory");
    }
    const float lw0 = lw[n * 3 + 0], lw1 = lw[n * 3 + 1], lw2 = lw[n * 3 + 2];
    const float lbn = lb[n];
    const float* up = u_begin + ((size_t)n * NN + c0 + tid) * 3;
    float u0 = up[0], u1 = up[1], u2 = up[2];
    float* op = out + (size_t)n * NN + c0 + tid;

#if __CUDA_ARCH__ >= 900
    cudaGridDependencySynchronize();          // wait for f_kernel before touching gF
#endif
    for (int t = tid; t < TT; t += CH) Fs[t] = gF[(size_t)n * TT + t];

    asm volatile("cp.async.wait_group 5;\n" ::: "memory");   // pair 0 (stages 0,1) arrived
    __syncthreads();                                          // (also publishes Fs)

    for (int i = 0; i < SS / 2; i++) {
        const int s0 = 2 * i;

        #pragma unroll
        for (int j = 0; j < 2; j++) {
            const int s = s0 + j;
            const float* st0 = stages[s & (NSTAGE - 1)];
            const float* st1 = st0 + CH * 3;
            const float a00 = st0[3 * tid], a01 = st0[3 * tid + 1], a02 = st0[3 * tid + 2];
            const float a10 = st1[3 * tid], a11 = st1[3 * tid + 1], a12 = st1[3 * tid + 2];
            const float2 fp = *(const float2*)&Fs[2 * s];     // one LDS.64, 8B-aligned
            const float f0 = fp.x, f1 = fp.y;

            float l0 = u0 + a00 * f0 + a10 * f1;
            float l1 = u1 + a01 * f0 + a11 * f1;
            float l2 = u2 + a02 * f0 + a12 * f1;
            // l0-referenced softmax: softmax = (1, e^d1, e^d2) / (1 + e^d1 + e^d2)
            float e1 = __expf(l1 - l0);
            float e2 = __expf(l2 - l0);
            float inv = __fdividef(1.0f, 1.0f + e1 + e2);
            u0 = inv;
            u1 = e1 * inv;
            u2 = e2 * inv;
            __stcs(op + (size_t)s * NN * NN,
                   fmaf(inv, lw0 + e1 * lw1 + e2 * lw2, lbn));
        }

        // refill pair (s0+12, s0+13): slot 12 ahead mod 16 -> disjoint from slots
        // read this interval and the 5 in-flight pairs
        if (s0 + 12 < SS) issue_stage(s0 + 12);
        if (s0 + 13 < SS) issue_stage(s0 + 13);
        asm volatile("cp.async.commit_group;\n" ::: "memory");   // (empty near tail)
        asm volatile("cp.async.wait_group 5;\n" ::: "memory");   // pair (s0+2,s0+3) arrived
        __syncthreads();
    }
}

extern "C" void kernel_launch(void* const* d_in, const int* in_sizes, int n_in,
                              void* d_out, int out_size)
{
    const float* time    = (const float*)d_in[0];   // [2]
    const float* ev      = (const float*)d_in[1];   // [201,256,256]
    const float* u_begin = (const float*)d_in[2];   // [256,256,3]
    const float* a       = (const float*)d_in[3];   // [200,256,256,3]
    const float* w       = (const float*)d_in[4];   // [200,256,1,256]
    const float* lw      = (const float*)d_in[5];   // [256,3]
    const float* lb      = (const float*)d_in[6];   // [256]

    float* out = (float*)d_out;                     // [100,256,256]

    f_kernel<<<(TT * NN / 2) / 8, 256>>>(time, ev, w);

    // PDL: scan launches early; its 12-stage cp.async prologue overlaps f_kernel.
    cudaLaunchConfig_t cfg = {};
    cfg.gridDim  = dim3(NN * 4);
    cfg.blockDim = dim3(CH);
    cudaLaunchAttribute attr[1];
    attr[0].id = cudaLaunchAttributeProgrammaticStreamSerialization;
    attr[0].val.programmaticStreamSerializationAllowed = 1;
    cfg.attrs = attr;
    cfg.numAttrs = 1;
    cudaLaunchKernelEx(&cfg, scan_kernel, u_begin, a, lw, lb, out);
}